// round 1
// baseline (speedup 1.0000x reference)
#include <cuda_runtime.h>

// Problem constants (fixed by the reference: B_SZ=2, SEQ=4096, D=4096, R=8, U=4)
#define D_DIM 4096
#define R_DIM 8
#define U_DIM 4
#define THREADS 256

// out[n, :] = base[n, :] + A @ (scale * (B @ x[n, :])),  scale = P @ v
// One block per row n. Phase 1: t[r] = sum_d B[r,d]*x[n,d] (block reduction).
// Phase 2: out[n,d] = base[n,d] + sum_r t[r]*scale[r]*A[d,r].
__global__ __launch_bounds__(THREADS, 8)
void tinylora_fused_kernel(const float* __restrict__ x,
                           const float* __restrict__ base,
                           const float* __restrict__ A,   // (D, R) row-major
                           const float* __restrict__ B,   // (R, D) row-major
                           const float* __restrict__ P,   // (R, U)
                           const float* __restrict__ v,   // (U,)
                           float* __restrict__ out)
{
    const int row = blockIdx.x;
    const int tid = threadIdx.x;
    const int lane = tid & 31;
    const int warp = tid >> 5;

    __shared__ float s_scale[R_DIM];
    __shared__ float s_part[8][R_DIM];   // 8 warps x 8 r
    __shared__ float s_t[R_DIM];

    // scale = P @ v  (tiny, recomputed per block — 32 FMAs)
    if (tid < R_DIM) {
        float s = 0.f;
        #pragma unroll
        for (int u = 0; u < U_DIM; u++) s += P[tid * U_DIM + u] * v[u];
        s_scale[tid] = s;
    }
    __syncthreads();

    // ---- Phase 1: t[r] = B[r,:] . x[row,:] ----
    const float4* __restrict__ x4 = reinterpret_cast<const float4*>(x + (size_t)row * D_DIM);
    const float4* __restrict__ B4 = reinterpret_cast<const float4*>(B);
    // D/4 = 1024 float4; 256 threads -> 4 float4 per thread
    float acc[R_DIM];
    #pragma unroll
    for (int r = 0; r < R_DIM; r++) acc[r] = 0.f;

    #pragma unroll
    for (int k = 0; k < 4; k++) {
        const int i4 = tid + k * THREADS;          // float4 index within the row
        const float4 xv = x4[i4];
        #pragma unroll
        for (int r = 0; r < R_DIM; r++) {
            const float4 bv = B4[r * (D_DIM / 4) + i4];
            acc[r] += xv.x * bv.x + xv.y * bv.y + xv.z * bv.z + xv.w * bv.w;
        }
    }

    // warp reduction
    #pragma unroll
    for (int r = 0; r < R_DIM; r++) {
        #pragma unroll
        for (int off = 16; off > 0; off >>= 1)
            acc[r] += __shfl_xor_sync(0xFFFFFFFFu, acc[r], off);
    }
    if (lane == 0) {
        #pragma unroll
        for (int r = 0; r < R_DIM; r++) s_part[warp][r] = acc[r];
    }
    __syncthreads();

    // cross-warp: threads 0..7 each own one r
    if (tid < R_DIM) {
        float s = 0.f;
        #pragma unroll
        for (int w = 0; w < 8; w++) s += s_part[w][tid];
        s_t[tid] = s * s_scale[tid];
    }
    __syncthreads();

    float t[R_DIM];
    #pragma unroll
    for (int r = 0; r < R_DIM; r++) t[r] = s_t[r];

    // ---- Phase 2: out[row,d] = base[row,d] + sum_r t[r] * A[d,r] ----
    const float* __restrict__ base_row = base + (size_t)row * D_DIM;
    float* __restrict__ out_row = out + (size_t)row * D_DIM;
    const float4* __restrict__ A4 = reinterpret_cast<const float4*>(A);

    #pragma unroll
    for (int k = 0; k < 16; k++) {
        const int d = tid + k * THREADS;
        const float4 a0 = A4[d * 2 + 0];   // A[d, 0..3]
        const float4 a1 = A4[d * 2 + 1];   // A[d, 4..7]
        float r = base_row[d];
        r += t[0] * a0.x + t[1] * a0.y + t[2] * a0.z + t[3] * a0.w;
        r += t[4] * a1.x + t[5] * a1.y + t[6] * a1.z + t[7] * a1.w;
        out_row[d] = r;
    }
}

extern "C" void kernel_launch(void* const* d_in, const int* in_sizes, int n_in,
                              void* d_out, int out_size)
{
    const float* x    = (const float*)d_in[0];
    const float* base = (const float*)d_in[1];
    const float* A    = (const float*)d_in[2];
    const float* B    = (const float*)d_in[3];
    const float* P    = (const float*)d_in[4];
    const float* v    = (const float*)d_in[5];
    float* out = (float*)d_out;

    const int n_rows = in_sizes[0] / D_DIM;   // B_SZ*SEQ = 8192
    tinylora_fused_kernel<<<n_rows, THREADS>>>(x, base, A, B, P, v, out);
}

// round 2
// speedup vs baseline: 1.0297x; 1.0297x over previous
#include <cuda_runtime.h>

// Problem constants (fixed: B_SZ=2, SEQ=4096, D=4096, R=8, U=4)
#define D_DIM 4096
#define D4    (D_DIM / 4)      // 1024 float4 per row
#define R_DIM 8
#define U_DIM 4
#define THREADS 256
#define M_ROWS 4               // rows per block: amortizes A/B L1 traffic 4x

// out[n,:] = base[n,:] + A @ (scale * (B @ x[n,:])),  scale = P @ v
// One block per M_ROWS rows. A and B (128 KB each) stay L1/L2-hot; loading
// each element once per block instead of once per row cuts L1 amplification
// from 6.3x to 2.3x, moving the kernel from L1-bound to DRAM-bound.
__global__ __launch_bounds__(THREADS)
void tinylora_fused_kernel(const float* __restrict__ x,
                           const float* __restrict__ base,
                           const float* __restrict__ A,   // (D, R) row-major
                           const float* __restrict__ B,   // (R, D) row-major
                           const float* __restrict__ P,   // (R, U)
                           const float* __restrict__ v,   // (U,)
                           float* __restrict__ out)
{
    const int row0 = blockIdx.x * M_ROWS;
    const int tid  = threadIdx.x;
    const int lane = tid & 31;
    const int warp = tid >> 5;

    __shared__ float s_scale[R_DIM];
    __shared__ float s_part[8][M_ROWS][R_DIM];  // 8 warps x 4 rows x 8 r = 1 KB
    __shared__ float s_t[M_ROWS][R_DIM];

    // scale = P @ v (32 FMAs, negligible)
    if (tid < R_DIM) {
        float s = 0.f;
        #pragma unroll
        for (int u = 0; u < U_DIM; u++) s += P[tid * U_DIM + u] * v[u];
        s_scale[tid] = s;
    }
    __syncthreads();

    // ---- Phase 1: t[m][r] = B[r,:] . x[row0+m,:] ----
    const float4* __restrict__ x4 = reinterpret_cast<const float4*>(x);
    const float4* __restrict__ B4 = reinterpret_cast<const float4*>(B);

    float acc[M_ROWS][R_DIM];
    #pragma unroll
    for (int m = 0; m < M_ROWS; m++)
        #pragma unroll
        for (int r = 0; r < R_DIM; r++) acc[m][r] = 0.f;

    #pragma unroll
    for (int k = 0; k < D4 / THREADS; k++) {           // 4 iterations
        const int i4 = tid + k * THREADS;
        float4 xv[M_ROWS];
        #pragma unroll
        for (int m = 0; m < M_ROWS; m++)
            xv[m] = x4[(size_t)(row0 + m) * D4 + i4];
        #pragma unroll
        for (int r = 0; r < R_DIM; r++) {
            const float4 bv = B4[r * D4 + i4];          // loaded once, used 4x
            #pragma unroll
            for (int m = 0; m < M_ROWS; m++)
                acc[m][r] += xv[m].x * bv.x + xv[m].y * bv.y
                           + xv[m].z * bv.z + xv[m].w * bv.w;
        }
    }

    // warp reduction (32 values x 5 levels)
    #pragma unroll
    for (int m = 0; m < M_ROWS; m++)
        #pragma unroll
        for (int r = 0; r < R_DIM; r++)
            #pragma unroll
            for (int off = 16; off > 0; off >>= 1)
                acc[m][r] += __shfl_xor_sync(0xFFFFFFFFu, acc[m][r], off);

    if (lane == 0) {
        #pragma unroll
        for (int m = 0; m < M_ROWS; m++)
            #pragma unroll
            for (int r = 0; r < R_DIM; r++) s_part[warp][m][r] = acc[m][r];
    }
    __syncthreads();

    // cross-warp combine: 32 threads, one (m, r) each
    if (tid < M_ROWS * R_DIM) {
        const int m = tid >> 3, r = tid & 7;
        float s = 0.f;
        #pragma unroll
        for (int w = 0; w < 8; w++) s += s_part[w][m][r];
        s_t[m][r] = s * s_scale[r];
    }
    __syncthreads();

    float t[M_ROWS][R_DIM];
    #pragma unroll
    for (int m = 0; m < M_ROWS; m++)
        #pragma unroll
        for (int r = 0; r < R_DIM; r++) t[m][r] = s_t[m][r];   // smem broadcast

    // ---- Phase 2: out[m][d] = base[m][d] + sum_r t[m][r] * A[d][r] ----
    const float4* __restrict__ A4    = reinterpret_cast<const float4*>(A);
    const float4* __restrict__ base4 = reinterpret_cast<const float4*>(base);
    float4* __restrict__ out4        = reinterpret_cast<float4*>(out);

    #pragma unroll
    for (int k = 0; k < D4 / THREADS; k++) {           // 4 iterations
        const int i4 = tid + k * THREADS;              // float4 group: d = 4*i4..4*i4+3
        // A rows for the 4 consecutive d's — loaded once, used for 4 rows
        float4 a[8];
        #pragma unroll
        for (int dd = 0; dd < 4; dd++) {
            a[2 * dd + 0] = A4[(size_t)(4 * i4 + dd) * 2 + 0];  // A[d, 0..3]
            a[2 * dd + 1] = A4[(size_t)(4 * i4 + dd) * 2 + 1];  // A[d, 4..7]
        }
        #pragma unroll
        for (int m = 0; m < M_ROWS; m++) {
            const size_t off = (size_t)(row0 + m) * D4 + i4;
            float4 bv = base4[off];
            float4 o;
            o.x = bv.x + t[m][0]*a[0].x + t[m][1]*a[0].y + t[m][2]*a[0].z + t[m][3]*a[0].w
                       + t[m][4]*a[1].x + t[m][5]*a[1].y + t[m][6]*a[1].z + t[m][7]*a[1].w;
            o.y = bv.y + t[m][0]*a[2].x + t[m][1]*a[2].y + t[m][2]*a[2].z + t[m][3]*a[2].w
                       + t[m][4]*a[3].x + t[m][5]*a[3].y + t[m][6]*a[3].z + t[m][7]*a[3].w;
            o.z = bv.z + t[m][0]*a[4].x + t[m][1]*a[4].y + t[m][2]*a[4].z + t[m][3]*a[4].w
                       + t[m][4]*a[5].x + t[m][5]*a[5].y + t[m][6]*a[5].z + t[m][7]*a[5].w;
            o.w = bv.w + t[m][0]*a[6].x + t[m][1]*a[6].y + t[m][2]*a[6].z + t[m][3]*a[6].w
                       + t[m][4]*a[7].x + t[m][5]*a[7].y + t[m][6]*a[7].z + t[m][7]*a[7].w;
            out4[off] = o;
        }
    }
}

extern "C" void kernel_launch(void* const* d_in, const int* in_sizes, int n_in,
                              void* d_out, int out_size)
{
    const float* x    = (const float*)d_in[0];
    const float* base = (const float*)d_in[1];
    const float* A    = (const float*)d_in[2];
    const float* B    = (const float*)d_in[3];
    const float* P    = (const float*)d_in[4];
    const float* v    = (const float*)d_in[5];
    float* out = (float*)d_out;

    const int n_rows = in_sizes[0] / D_DIM;   // 8192
    tinylora_fused_kernel<<<n_rows / M_ROWS, THREADS>>>(x, base, A, B, P, v, out);
}

// round 3
// speedup vs baseline: 1.1798x; 1.1458x over previous
#include <cuda_runtime.h>

// Problem constants (fixed: B_SZ=2, SEQ=4096, D=4096, R=8, U=4)
#define D_DIM  4096
#define D4     1024          // float4 per row
#define R_DIM  8
#define U_DIM  4
#define N_ROWS 8192

// Scratch for t = scale * (B @ x^T): 8192 x 8 floats = 256 KB (static, allowed)
__device__ float g_t[N_ROWS * R_DIM];

// ======================= Phase 1: t[n,r] = scale[r] * (B[r,:] . x[n,:]) =====
// Block: 256 threads = 32 rows x 8 ranks, one fp32 accumulator per thread.
// x and B staged through smem in 128-float k-tiles with register prefetch.
#define P1_THREADS 256
#define MT  32               // rows per block
#define KC4 32               // k-tile size in float4 (=128 floats)

__global__ __launch_bounds__(P1_THREADS)
void phase1_kernel(const float* __restrict__ x,
                   const float* __restrict__ B,
                   const float* __restrict__ P,
                   const float* __restrict__ v)
{
    __shared__ float4 xs[MT][KC4 + 1];      // +1 float4 pad: conflict-free
    __shared__ float4 bs[R_DIM][KC4 + 1];

    const int tid  = threadIdx.x;
    const int m    = tid >> 3;              // row within tile (0..31)
    const int r    = tid & 7;               // rank (0..7)
    const int row0 = blockIdx.x * MT;

    const float4* __restrict__ x4 = reinterpret_cast<const float4*>(x);
    const float4* __restrict__ B4 = reinterpret_cast<const float4*>(B);

    const int lr = tid >> 5;                // B-loader row (0..7)
    const int lc = tid & 31;                // B-loader col (0..31)

    float acc = 0.f;

    // prefetch tile 0 into registers
    float4 px[4];
    float4 pb;
    #pragma unroll
    for (int i = 0; i < 4; i++) {
        const int f = tid + i * P1_THREADS;                 // 0..1023
        px[i] = x4[(size_t)(row0 + (f >> 5)) * D4 + (f & 31)];
    }
    pb = B4[lr * D4 + lc];

    #pragma unroll 1
    for (int kt = 0; kt < D4 / KC4; kt++) {                 // 32 k-tiles
        // commit prefetched tile to smem
        #pragma unroll
        for (int i = 0; i < 4; i++) {
            const int f = tid + i * P1_THREADS;
            xs[f >> 5][f & 31] = px[i];
        }
        bs[lr][lc] = pb;
        __syncthreads();

        // issue next tile's global loads (overlap with compute)
        if (kt + 1 < D4 / KC4) {
            const int kbase = (kt + 1) * KC4;
            #pragma unroll
            for (int i = 0; i < 4; i++) {
                const int f = tid + i * P1_THREADS;
                px[i] = x4[(size_t)(row0 + (f >> 5)) * D4 + kbase + (f & 31)];
            }
            pb = B4[lr * D4 + kbase + lc];
        }

        // compute: 32 float4 dot-products (broadcast-friendly smem reads)
        #pragma unroll
        for (int kk = 0; kk < KC4; kk++) {
            const float4 xv = xs[m][kk];
            const float4 bv = bs[r][kk];
            acc += xv.x * bv.x + xv.y * bv.y + xv.z * bv.z + xv.w * bv.w;
        }
        __syncthreads();
    }

    // scale[r] = P[r,:] . v  (4 FMAs per thread, L1-hot)
    float s = 0.f;
    #pragma unroll
    for (int u = 0; u < U_DIM; u++) s += P[r * U_DIM + u] * v[u];

    g_t[(size_t)(row0 + m) * R_DIM + r] = acc * s;          // coalesced
}

// ======================= Phase 2: out[n,d] = base[n,d] + sum_r t[n,r]*A[d,r] =
// Block: 256 threads, tile = NT rows x 1024 columns. Each thread pins its
// 4 columns' A rows (8 float4 = 32 regs) and streams NT rows of base->out.
#define P2_THREADS 256
#define NT 16                 // rows per block
#define DT4 256               // float4 columns per block (=1024 floats)

__global__ __launch_bounds__(P2_THREADS)
void phase2_kernel(const float* __restrict__ base,
                   const float* __restrict__ A,
                   float* __restrict__ out)
{
    __shared__ float ts[NT][R_DIM];         // 512 B

    const int tid   = threadIdx.x;
    const int row0  = blockIdx.x * NT;
    const int d4_0  = blockIdx.y * DT4;

    const float4* __restrict__ A4    = reinterpret_cast<const float4*>(A);
    const float4* __restrict__ base4 = reinterpret_cast<const float4*>(base);
    float4* __restrict__ out4        = reinterpret_cast<float4*>(out);

    // t tile for these NT rows (NT*8 = 128 floats)
    if (tid < NT * R_DIM)
        ts[tid >> 3][tid & 7] = g_t[(size_t)(row0 + (tid >> 3)) * R_DIM + (tid & 7)];

    // A rows for this thread's 4 consecutive d's: 128 contiguous bytes
    const int d4 = d4_0 + tid;              // this thread's float4 column
    float4 a[8];
    #pragma unroll
    for (int j = 0; j < 8; j++)
        a[j] = A4[(size_t)d4 * 8 + j];      // A[4*d4 + j/2, (j&1)*4 .. +3]

    __syncthreads();

    #pragma unroll
    for (int mm = 0; mm < NT; mm++) {
        const size_t off = (size_t)(row0 + mm) * D4 + d4;
        const float4 bv = base4[off];
        float t0 = ts[mm][0], t1 = ts[mm][1], t2 = ts[mm][2], t3 = ts[mm][3];
        float t4 = ts[mm][4], t5 = ts[mm][5], t6 = ts[mm][6], t7 = ts[mm][7];
        float4 o;
        o.x = bv.x + t0*a[0].x + t1*a[0].y + t2*a[0].z + t3*a[0].w
                   + t4*a[1].x + t5*a[1].y + t6*a[1].z + t7*a[1].w;
        o.y = bv.y + t0*a[2].x + t1*a[2].y + t2*a[2].z + t3*a[2].w
                   + t4*a[3].x + t5*a[3].y + t6*a[3].z + t7*a[3].w;
        o.z = bv.z + t0*a[4].x + t1*a[4].y + t2*a[4].z + t3*a[4].w
                   + t4*a[5].x + t5*a[5].y + t6*a[5].z + t7*a[5].w;
        o.w = bv.w + t0*a[6].x + t1*a[6].y + t2*a[6].z + t3*a[6].w
                   + t4*a[7].x + t5*a[7].y + t6*a[7].z + t7*a[7].w;
        out4[off] = o;
    }
}

extern "C" void kernel_launch(void* const* d_in, const int* in_sizes, int n_in,
                              void* d_out, int out_size)
{
    const float* x    = (const float*)d_in[0];
    const float* base = (const float*)d_in[1];
    const float* A    = (const float*)d_in[2];
    const float* B    = (const float*)d_in[3];
    const float* P    = (const float*)d_in[4];
    const float* v    = (const float*)d_in[5];
    float* out = (float*)d_out;

    phase1_kernel<<<N_ROWS / MT, P1_THREADS>>>(x, B, P, v);
    dim3 g2(N_ROWS / NT, D_DIM / (DT4 * 4));
    phase2_kernel<<<g2, P2_THREADS>>>(base, A, out);
}

// round 4
// speedup vs baseline: 1.2625x; 1.0701x over previous
#include <cuda_runtime.h>

// Problem constants (fixed: B_SZ=2, SEQ=4096, D=4096, R=8, U=4)
#define D_DIM  4096
#define D4     1024          // float4 per row
#define R_DIM  8
#define U_DIM  4
#define N_ROWS 8192

// Scratch for t = scale * (B @ x^T): 8192 x 8 floats = 256 KB (static, allowed)
__device__ float g_t[N_ROWS * R_DIM];

// ======================= Phase 1: t[n,r] = scale[r] * (B[r,:] . x[n,:]) =====
// Outer-product register blocking: thread owns a 4x2 (m x r) sub-tile ->
// 6 LDS.128 per 32 FMAs (was 2 per 4). 8 warps split each k-tile (split-k),
// cross-warp reduction at the end through smem.
#define P1_THREADS 256
#define MT   32              // rows per block
#define KC4  32              // k-tile size in float4 (=128 floats)
#define WSL  (KC4 / 8)       // k-slice per warp within a tile = 4 float4

__global__ __launch_bounds__(P1_THREADS)
void phase1_kernel(const float* __restrict__ x,
                   const float* __restrict__ B,
                   const float* __restrict__ P,
                   const float* __restrict__ v)
{
    __shared__ float4 xs[MT][KC4 + 1];        // 16.9 KB, pad: conflict-free
    __shared__ float4 bs[R_DIM][KC4 + 1];     // 4.2 KB
    __shared__ float  s_part[8][MT][R_DIM];   // 8 KB: per-warp split-k partials

    const int tid  = threadIdx.x;
    const int w    = tid >> 5;                // warp id (k-slice owner)
    const int lane = tid & 31;
    const int m0   = (lane >> 2) * 4;         // 8 m-groups x 4 rows
    const int r0   = (lane & 3) * 2;          // 4 r-groups x 2 ranks
    const int row0 = blockIdx.x * MT;

    const float4* __restrict__ x4 = reinterpret_cast<const float4*>(x);
    const float4* __restrict__ B4 = reinterpret_cast<const float4*>(B);

    float acc[4][2];
    #pragma unroll
    for (int i = 0; i < 4; i++)
        #pragma unroll
        for (int j = 0; j < 2; j++) acc[i][j] = 0.f;

    // prefetch tile 0 into registers (coalesced: warp reads 512B runs)
    float4 px[4];
    float4 pb;
    #pragma unroll
    for (int i = 0; i < 4; i++) {
        const int f = tid + i * P1_THREADS;                  // 0..1023
        px[i] = x4[(size_t)(row0 + (f >> 5)) * D4 + (f & 31)];
    }
    pb = B4[(tid >> 5) * D4 + (tid & 31)];

    #pragma unroll 1
    for (int kt = 0; kt < D4 / KC4; kt++) {                  // 32 k-tiles
        #pragma unroll
        for (int i = 0; i < 4; i++) {
            const int f = tid + i * P1_THREADS;
            xs[f >> 5][f & 31] = px[i];
        }
        bs[tid >> 5][tid & 31] = pb;
        __syncthreads();

        // issue next tile's global loads (overlap with compute)
        if (kt + 1 < D4 / KC4) {
            const int kbase = (kt + 1) * KC4;
            #pragma unroll
            for (int i = 0; i < 4; i++) {
                const int f = tid + i * P1_THREADS;
                px[i] = x4[(size_t)(row0 + (f >> 5)) * D4 + kbase + (f & 31)];
            }
            pb = B4[(tid >> 5) * D4 + kbase + (tid & 31)];
        }

        // compute: warp w handles kk in [w*WSL, w*WSL+WSL)
        #pragma unroll
        for (int i = 0; i < WSL; i++) {
            const int kk = w * WSL + i;
            float4 xv[4], bv[2];
            #pragma unroll
            for (int a = 0; a < 4; a++) xv[a] = xs[m0 + a][kk];
            #pragma unroll
            for (int b = 0; b < 2; b++) bv[b] = bs[r0 + b][kk];
            #pragma unroll
            for (int a = 0; a < 4; a++)
                #pragma unroll
                for (int b = 0; b < 2; b++)
                    acc[a][b] += xv[a].x * bv[b].x + xv[a].y * bv[b].y
                               + xv[a].z * bv[b].z + xv[a].w * bv[b].w;
        }
        __syncthreads();
    }

    // cross-warp (split-k) reduction
    #pragma unroll
    for (int a = 0; a < 4; a++)
        #pragma unroll
        for (int b = 0; b < 2; b++)
            s_part[w][m0 + a][r0 + b] = acc[a][b];
    __syncthreads();

    // 256 threads: one (m, r) each
    const int m = tid >> 3;
    const int r = tid & 7;
    float s = 0.f;
    #pragma unroll
    for (int ww = 0; ww < 8; ww++) s += s_part[ww][m][r];

    // scale[r] = P[r,:] . v
    float sc = 0.f;
    #pragma unroll
    for (int u = 0; u < U_DIM; u++) sc += P[r * U_DIM + u] * v[u];

    g_t[(size_t)(row0 + m) * R_DIM + r] = s * sc;            // coalesced
}

// ======================= Phase 2: out[n,d] = base[n,d] + sum_r t[n,r]*A[d,r] =
// Block: 256 threads, tile = NT rows x 1024 columns. Thread pins its 4
// columns' A rows (8 float4) and streams NT rows of base->out.
// launch_bounds(256,4): cap 64 regs -> 4 blocks/SM for MLP/occupancy.
#define P2_THREADS 256
#define NT  16                // rows per block
#define DT4 256               // float4 columns per block (=1024 floats)

__global__ __launch_bounds__(P2_THREADS, 4)
void phase2_kernel(const float* __restrict__ base,
                   const float* __restrict__ A,
                   float* __restrict__ out)
{
    __shared__ float ts[NT][R_DIM];           // 512 B

    const int tid  = threadIdx.x;
    const int row0 = blockIdx.y * NT;
    const int d4   = blockIdx.x * DT4 + tid;  // this thread's float4 column

    const float4* __restrict__ A4    = reinterpret_cast<const float4*>(A);
    const float4* __restrict__ base4 = reinterpret_cast<const float4*>(base);
    float4* __restrict__ out4        = reinterpret_cast<float4*>(out);

    if (tid < NT * R_DIM)
        ts[tid >> 3][tid & 7] = g_t[(size_t)(row0 + (tid >> 3)) * R_DIM + (tid & 7)];

    // A rows for this thread's 4 consecutive d's: 128 contiguous bytes
    float4 a[8];
    #pragma unroll
    for (int j = 0; j < 8; j++)
        a[j] = A4[(size_t)d4 * 8 + j];

    __syncthreads();

    #pragma unroll
    for (int mm = 0; mm < NT; mm++) {
        const size_t off = (size_t)(row0 + mm) * D4 + d4;
        const float4 bv = base4[off];
        const float t0 = ts[mm][0], t1 = ts[mm][1], t2 = ts[mm][2], t3 = ts[mm][3];
        const float t4 = ts[mm][4], t5 = ts[mm][5], t6 = ts[mm][6], t7 = ts[mm][7];
        float4 o;
        o.x = bv.x + t0*a[0].x + t1*a[0].y + t2*a[0].z + t3*a[0].w
                   + t4*a[1].x + t5*a[1].y + t6*a[1].z + t7*a[1].w;
        o.y = bv.y + t0*a[2].x + t1*a[2].y + t2*a[2].z + t3*a[2].w
                   + t4*a[3].x + t5*a[3].y + t6*a[3].z + t7*a[3].w;
        o.z = bv.z + t0*a[4].x + t1*a[4].y + t2*a[4].z + t3*a[4].w
                   + t4*a[5].x + t5*a[5].y + t6*a[5].z + t7*a[5].w;
        o.w = bv.w + t0*a[6].x + t1*a[6].y + t2*a[6].z + t3*a[6].w
                   + t4*a[7].x + t5*a[7].y + t6*a[7].z + t7*a[7].w;
        out4[off] = o;
    }
}

extern "C" void kernel_launch(void* const* d_in, const int* in_sizes, int n_in,
                              void* d_out, int out_size)
{
    const float* x    = (const float*)d_in[0];
    const float* base = (const float*)d_in[1];
    const float* A    = (const float*)d_in[2];
    const float* B    = (const float*)d_in[3];
    const float* P    = (const float*)d_in[4];
    const float* v    = (const float*)d_in[5];
    float* out = (float*)d_out;

    phase1_kernel<<<N_ROWS / MT, P1_THREADS>>>(x, B, P, v);
    dim3 g2(D_DIM / (DT4 * 4), N_ROWS / NT);   // (4, 512)
    phase2_kernel<<<g2, P2_THREADS>>>(base, A, out);
}

// round 5
// speedup vs baseline: 1.2931x; 1.0242x over previous
#include <cuda_runtime.h>

// Problem constants (fixed: B_SZ=2, SEQ=4096, D=4096, R=8, U=4)
#define D_DIM  4096
#define D4     1024          // float4 per row
#define R_DIM  8
#define U_DIM  4
#define N_ROWS 8192

// Scratch for t = scale * (B @ x^T): 8192 x 8 floats = 256 KB (static, allowed)
__device__ float g_t[N_ROWS * R_DIM];

// ======================= Phase 1: t[n,r] = scale[r] * (B[r,:] . x[n,:]) =====
// Smem-free: each warp owns RPW=4 rows, lanes split the k dimension (lane =
// float4 offset within a 128-float k-tile). x loads are coalesced 512B runs
// streamed once from DRAM; B (128 KB) is L1/L2-hot. No barriers, no smem in
// the main loop. Final cross-lane reduction via butterfly shuffles.
#define P1_THREADS 256
#define RPW 4                // rows per warp
#define P1_ROWS_PER_BLOCK (RPW * (P1_THREADS / 32))   // 32

__global__ __launch_bounds__(P1_THREADS)
void phase1_kernel(const float* __restrict__ x,
                   const float* __restrict__ B,
                   const float* __restrict__ P,
                   const float* __restrict__ v)
{
    const int tid  = threadIdx.x;
    const int w    = tid >> 5;
    const int lane = tid & 31;
    const int row0 = blockIdx.x * P1_ROWS_PER_BLOCK + w * RPW;

    const float4* __restrict__ x4 = reinterpret_cast<const float4*>(x);
    const float4* __restrict__ B4 = reinterpret_cast<const float4*>(B);

    float acc[RPW][R_DIM];
    #pragma unroll
    for (int a = 0; a < RPW; a++)
        #pragma unroll
        for (int r = 0; r < R_DIM; r++) acc[a][r] = 0.f;

    #pragma unroll 2
    for (int kt = 0; kt < D4 / 32; kt++) {        // 32 k-tiles of 32 float4
        const int i4 = kt * 32 + lane;
        float4 xv[RPW];
        #pragma unroll
        for (int a = 0; a < RPW; a++)
            xv[a] = x4[(size_t)(row0 + a) * D4 + i4];   // coalesced, DRAM stream
        #pragma unroll
        for (int r = 0; r < R_DIM; r++) {
            const float4 bv = B4[r * D4 + i4];          // L1-hot
            #pragma unroll
            for (int a = 0; a < RPW; a++)
                acc[a][r] += xv[a].x * bv.x + xv[a].y * bv.y
                           + xv[a].z * bv.z + xv[a].w * bv.w;
        }
    }

    // Butterfly-reduce each of the 32 accumulators across the warp's lanes.
    #pragma unroll
    for (int a = 0; a < RPW; a++)
        #pragma unroll
        for (int r = 0; r < R_DIM; r++)
            #pragma unroll
            for (int off = 16; off > 0; off >>= 1)
                acc[a][r] += __shfl_xor_sync(0xFFFFFFFFu, acc[a][r], off);

    // Lane l writes (a = l>>3, r = l&7): 32 consecutive floats = 128B coalesced.
    const int a = lane >> 3;
    const int r = lane & 7;
    float sc = 0.f;
    #pragma unroll
    for (int u = 0; u < U_DIM; u++) sc += P[r * U_DIM + u] * v[u];
    g_t[(size_t)(row0 + a) * R_DIM + r] = acc[a][r] * sc;
}

// ======================= Phase 2: out[n,d] = base[n,d] + sum_r t[n,r]*A[d,r] =
// Block = NT2 rows x 1024 cols. Thread pins A rows for its 4 consecutive d's
// (8 float4 = 32 regs) and streams rows in chunks of 4 with batched base
// loads (MLP=4). No register cap — ILP beats occupancy here (R4 lesson).
// Grid: blockIdx.x = row tile (concurrent blocks share the same A slice).
#define P2_THREADS 256
#define NT2 32                // rows per block
#define DT4 256               // float4 columns per block

__global__ __launch_bounds__(P2_THREADS)
void phase2_kernel(const float* __restrict__ base,
                   const float* __restrict__ A,
                   float* __restrict__ out)
{
    __shared__ float ts[NT2][R_DIM];          // 1 KB

    const int tid  = threadIdx.x;
    const int row0 = blockIdx.x * NT2;
    const int d4   = blockIdx.y * DT4 + tid;  // this thread's float4 column

    const float4* __restrict__ A4    = reinterpret_cast<const float4*>(A);
    const float4* __restrict__ base4 = reinterpret_cast<const float4*>(base);
    float4* __restrict__ out4        = reinterpret_cast<float4*>(out);

    // t tile: NT2*8 = 256 floats, one per thread
    ts[tid >> 3][tid & 7] = g_t[(size_t)(row0 + (tid >> 3)) * R_DIM + (tid & 7)];

    // A rows for this thread's 4 consecutive d's: 128 contiguous bytes
    float4 a[8];
    #pragma unroll
    for (int j = 0; j < 8; j++)
        a[j] = A4[(size_t)d4 * 8 + j];

    __syncthreads();

    #pragma unroll 2
    for (int c = 0; c < NT2; c += 4) {
        // batch 4 independent base loads (MLP=4)
        float4 bv[4];
        #pragma unroll
        for (int i = 0; i < 4; i++)
            bv[i] = base4[(size_t)(row0 + c + i) * D4 + d4];

        #pragma unroll
        for (int i = 0; i < 4; i++) {
            const int mm = c + i;
            const float t0 = ts[mm][0], t1 = ts[mm][1], t2 = ts[mm][2], t3 = ts[mm][3];
            const float t4 = ts[mm][4], t5 = ts[mm][5], t6 = ts[mm][6], t7 = ts[mm][7];
            float4 o;
            o.x = bv[i].x + t0*a[0].x + t1*a[0].y + t2*a[0].z + t3*a[0].w
                          + t4*a[1].x + t5*a[1].y + t6*a[1].z + t7*a[1].w;
            o.y = bv[i].y + t0*a[2].x + t1*a[2].y + t2*a[2].z + t3*a[2].w
                          + t4*a[3].x + t5*a[3].y + t6*a[3].z + t7*a[3].w;
            o.z = bv[i].z + t0*a[4].x + t1*a[4].y + t2*a[4].z + t3*a[4].w
                          + t4*a[5].x + t5*a[5].y + t6*a[5].z + t7*a[5].w;
            o.w = bv[i].w + t0*a[6].x + t1*a[6].y + t2*a[6].z + t3*a[6].w
                          + t4*a[7].x + t5*a[7].y + t6*a[7].z + t7*a[7].w;
            out4[(size_t)(row0 + mm) * D4 + d4] = o;
        }
    }
}

extern "C" void kernel_launch(void* const* d_in, const int* in_sizes, int n_in,
                              void* d_out, int out_size)
{
    const float* x    = (const float*)d_in[0];
    const float* base = (const float*)d_in[1];
    const float* A    = (const float*)d_in[2];
    const float* B    = (const float*)d_in[3];
    const float* P    = (const float*)d_in[4];
    const float* v    = (const float*)d_in[5];
    float* out = (float*)d_out;

    phase1_kernel<<<N_ROWS / P1_ROWS_PER_BLOCK, P1_THREADS>>>(x, B, P, v);
    dim3 g2(N_ROWS / NT2, D_DIM / (DT4 * 4));   // (256, 4), row-major block order
    phase2_kernel<<<g2, P2_THREADS>>>(base, A, out);
}

// round 7
// speedup vs baseline: 1.4439x; 1.1166x over previous
#include <cuda_runtime.h>

// Problem constants (fixed: B_SZ=2, SEQ=4096, D=4096, R=8, U=4)
#define D_DIM  4096
#define D4     1024          // float4 per row
#define R_DIM  8
#define U_DIM  4
#define N_ROWS 8192

#define SPLITK 4
#define KQ4    (D4 / SPLITK) // 256 float4 per k-quarter

// Split-k partials for t: 4 x 8192 x 8 floats = 1 MB (static, allowed).
// Phase 2 folds the 4 partials; no atomics, no zero-init needed.
__device__ float g_tp[SPLITK][N_ROWS * R_DIM];

// ======================= Phase 1: partial t over one k-quarter ==============
// Block = (rowTile, kq): 32 rows x 1024 k-elems. Warp owns 4 rows, lanes
// split k. Grid = 1024 blocks -> enough resident warps to hide DRAM latency
// (R5 had 256 blocks = 1.7/SM and was latency-starved). No smem, no barriers.
#define P1_THREADS 256
#define RPW 4                // rows per warp
#define P1_ROWS_PER_BLOCK (RPW * (P1_THREADS / 32))   // 32

__global__ __launch_bounds__(P1_THREADS)
void phase1_kernel(const float* __restrict__ x,
                   const float* __restrict__ B)
{
    const int tid  = threadIdx.x;
    const int w    = tid >> 5;
    const int lane = tid & 31;
    const int row0 = blockIdx.x * P1_ROWS_PER_BLOCK + w * RPW;
    const int kq   = blockIdx.y;
    const int kb4  = kq * KQ4;

    const float4* __restrict__ x4 = reinterpret_cast<const float4*>(x);
    const float4* __restrict__ B4 = reinterpret_cast<const float4*>(B);

    float acc[RPW][R_DIM];
    #pragma unroll
    for (int a = 0; a < RPW; a++)
        #pragma unroll
        for (int r = 0; r < R_DIM; r++) acc[a][r] = 0.f;

    #pragma unroll 2
    for (int kt = 0; kt < KQ4 / 32; kt++) {       // 8 k-tiles of 32 float4
        const int i4 = kb4 + kt * 32 + lane;
        float4 xv[RPW];
        #pragma unroll
        for (int a = 0; a < RPW; a++)
            xv[a] = __ldcs(&x4[(size_t)(row0 + a) * D4 + i4]);  // stream, no reuse
        #pragma unroll
        for (int r = 0; r < R_DIM; r++) {
            const float4 bv = B4[r * D4 + i4];                  // L1/L2-hot
            #pragma unroll
            for (int a = 0; a < RPW; a++)
                acc[a][r] += xv[a].x * bv.x + xv[a].y * bv.y
                           + xv[a].z * bv.z + xv[a].w * bv.w;
        }
    }

    // Butterfly-reduce the 32 accumulators across lanes.
    #pragma unroll
    for (int a = 0; a < RPW; a++)
        #pragma unroll
        for (int r = 0; r < R_DIM; r++)
            #pragma unroll
            for (int off = 16; off > 0; off >>= 1)
                acc[a][r] += __shfl_xor_sync(0xFFFFFFFFu, acc[a][r], off);

    // Lane l writes (a = l>>3, r = l&7): 128B coalesced per warp.
    const int a = lane >> 3;
    const int r = lane & 7;
    g_tp[kq][(size_t)(row0 + a) * R_DIM + r] = acc[a][r];
}

// ======================= Phase 2: out[n,d] = base[n,d] + sum_r t[n,r]*A[d,r] =
// Folds the 4 split-k partials and applies scale = P @ v while building the
// t-tile. Thread pins its 4 columns' A rows (8 float4) and streams NT2 rows
// with batched base loads (MLP=4). base/out use .cs (evict-first) — zero reuse.
#define P2_THREADS 256
#define NT2 32                // rows per block
#define DT4 256               // float4 columns per block

__global__ __launch_bounds__(P2_THREADS)
void phase2_kernel(const float* __restrict__ base,
                   const float* __restrict__ A,
                   const float* __restrict__ P,
                   const float* __restrict__ v,
                   float* __restrict__ out)
{
    __shared__ float ts[NT2][R_DIM];          // 1 KB

    const int tid  = threadIdx.x;
    const int row0 = blockIdx.x * NT2;
    const int d4   = blockIdx.y * DT4 + tid;  // this thread's float4 column

    const float4* __restrict__ A4    = reinterpret_cast<const float4*>(A);
    const float4* __restrict__ base4 = reinterpret_cast<const float4*>(base);
    float4* __restrict__ out4        = reinterpret_cast<float4*>(out);

    // Fold split-k partials + scale: thread owns one (m, r).
    {
        const int m = tid >> 3, r = tid & 7;
        const size_t idx = (size_t)(row0 + m) * R_DIM + r;
        float s = 0.f;
        #pragma unroll
        for (int q = 0; q < SPLITK; q++) s += g_tp[q][idx];
        float sc = 0.f;
        #pragma unroll
        for (int u = 0; u < U_DIM; u++) sc += P[r * U_DIM + u] * v[u];
        ts[m][r] = s * sc;
    }

    // A rows for this thread's 4 consecutive d's: 128 contiguous bytes.
    float4 a[8];
    #pragma unroll
    for (int j = 0; j < 8; j++)
        a[j] = A4[(size_t)d4 * 8 + j];

    __syncthreads();

    #pragma unroll 2
    for (int c = 0; c < NT2; c += 4) {
        float4 bv[4];                          // batch 4 loads (MLP=4)
        #pragma unroll
        for (int i = 0; i < 4; i++)
            bv[i] = __ldcs(&base4[(size_t)(row0 + c + i) * D4 + d4]);

        #pragma unroll
        for (int i = 0; i < 4; i++) {
            const int mm = c + i;
            const float t0 = ts[mm][0], t1 = ts[mm][1], t2 = ts[mm][2], t3 = ts[mm][3];
            const float t4 = ts[mm][4], t5 = ts[mm][5], t6 = ts[mm][6], t7 = ts[mm][7];
            float4 o;
            o.x = bv[i].x + t0*a[0].x + t1*a[0].y + t2*a[0].z + t3*a[0].w
                          + t4*a[1].x + t5*a[1].y + t6*a[1].z + t7*a[1].w;
            o.y = bv[i].y + t0*a[2].x + t1*a[2].y + t2*a[2].z + t3*a[2].w
                          + t4*a[3].x + t5*a[3].y + t6*a[3].z + t7*a[3].w;
            o.z = bv[i].z + t0*a[4].x + t1*a[4].y + t2*a[4].z + t3*a[4].w
                          + t4*a[5].x + t5*a[5].y + t6*a[5].z + t7*a[5].w;
            o.w = bv[i].w + t0*a[6].x + t1*a[6].y + t2*a[6].z + t3*a[6].w
                          + t4*a[7].x + t5*a[7].y + t6*a[7].z + t7*a[7].w;
            __stcs(&out4[(size_t)(row0 + mm) * D4 + d4], o);
        }
    }
}

extern "C" void kernel_launch(void* const* d_in, const int* in_sizes, int n_in,
                              void* d_out, int out_size)
{
    const float* x    = (const float*)d_in[0];
    const float* base = (const float*)d_in[1];
    const float* A    = (const float*)d_in[2];
    const float* B    = (const float*)d_in[3];
    const float* P    = (const float*)d_in[4];
    const float* v    = (const float*)d_in[5];
    float* out = (float*)d_out;

    dim3 g1(N_ROWS / P1_ROWS_PER_BLOCK, SPLITK);  // (256, 4) = 1024 blocks
    phase1_kernel<<<g1, P1_THREADS>>>(x, B);

    dim3 g2(N_ROWS / NT2, D_DIM / (DT4 * 4));     // (256, 4) = 1024 blocks
    phase2_kernel<<<g2, P2_THREADS>>>(base, A, P, v, out);
}